// round 9
// baseline (speedup 1.0000x reference)
#include <cuda_runtime.h>

#define MARGIN 0.2f
#define TPB   256
#define TJ    256          // j-tile (shared)
#define TI    1024         // i-supertile (4 per thread)
#define RATIO (TI / TJ)    // 4
#define NWARP 8
#define MAXGI 16

__device__ double g_rank_sum;                 // reset by last block each call
__device__ double g_mompart[MAXGI * 5];       // per-supertile moment partials
__device__ unsigned int g_done;               // reset by last block each call

// ---------------------------------------------------------------------------
// Single kernel. Grid enumerates blocks (I, J) with J in [RATIO*I, Gj):
//   i in [I*TI, I*TI+TI)  (4 per thread: i_q = I*TI + q*TPB + tid)
//   j in [J*TJ, J*TJ+TJ)  (staged in shared)
// Overlap blocks (J < RATIO*I + RATIO) mask pairs to j > i (exact).
// per_pair = (|dt| > m) ? relu(m - sign(dt)*dp) : 0.1*|dp|   (R3-validated)
// First-slice blocks (J == RATIO*I) also emit this supertile's moments.
// Last block finalizes the scalar and resets accumulators (replay-safe).
// ---------------------------------------------------------------------------
__global__ __launch_bounds__(TPB) void pair_kernel(const float* __restrict__ pr,
                                                   const float* __restrict__ tg,
                                                   int n, int Gi, int Gj, int T,
                                                   float* __restrict__ out) {
    __shared__ float2 sj[TJ];
    __shared__ double swd[NWARP];
    __shared__ double smom[5][NWARP];
    __shared__ double s_fin[MAXGI * 5];
    __shared__ bool   s_last;

    const int tid = threadIdx.x, lane = tid & 31, wid = tid >> 5;

    // ---- recover (I, J) from linear block id (Gi <= 16: tiny loop) ----
    int b = blockIdx.x;
    int I = 0, base = 0;
    for (;;) {
        int cnt = Gj - RATIO * I;          // >= 1 for every non-empty supertile
        if (b < base + cnt) break;
        base += cnt; ++I;
    }
    const int J = RATIO * I + (b - base);
    const bool overlap = (J < RATIO * I + RATIO);
    const bool momblk  = (J == RATIO * I);

    // ---- stage j-tile ----
    const int j0 = J * TJ;
    const int jcnt = min(TJ, n - j0);
    if (tid < jcnt) sj[tid] = make_float2(pr[j0 + tid], tg[j0 + tid]);
    __syncthreads();

    // ---- per-thread i state (4 rows, 256 apart) ----
    float p[4], t[4];
    bool  v[4];
    int   thr[4];
    #pragma unroll
    for (int q = 0; q < 4; q++) {
        int iq = I * TI + q * TPB + tid;
        v[q] = iq < n;
        p[q] = v[q] ? pr[iq] : 0.f;
        t[q] = v[q] ? tg[iq] : 0.f;
        thr[q] = iq - j0;                  // mask threshold (overlap blocks)
    }

    float acch[4] = {0.f, 0.f, 0.f, 0.f};
    float accm[4] = {0.f, 0.f, 0.f, 0.f};

    if (overlap) {
        #pragma unroll 2
        for (int k = 0; k < jcnt; k++) {
            float2 w = sj[k];
            #pragma unroll
            for (int q = 0; q < 4; q++) {
                if (k > thr[q]) {
                    float dp = p[q] - w.x;
                    float dt = t[q] - w.y;
                    float u  = __uint_as_float(__float_as_uint(dp) ^
                               (__float_as_uint(dt) & 0x80000000u));
                    float h  = fmaxf(MARGIN - u, 0.f);
                    if (fabsf(dt) > MARGIN) acch[q] += h;
                    else                    accm[q] += fabsf(dp);
                }
            }
        }
    } else {
        #pragma unroll 2
        for (int k = 0; k < jcnt; k++) {
            float2 w = sj[k];
            #pragma unroll
            for (int q = 0; q < 4; q++) {
                float dp = p[q] - w.x;
                float dt = t[q] - w.y;
                float u  = __uint_as_float(__float_as_uint(dp) ^
                           (__float_as_uint(dt) & 0x80000000u));
                float h  = fmaxf(MARGIN - u, 0.f);
                if (fabsf(dt) > MARGIN) acch[q] += h;
                else                    accm[q] += fabsf(dp);
            }
        }
    }

    // ---- moments (first-slice blocks own their supertile's i-range) ----
    if (momblk) {
        double m[5] = {0, 0, 0, 0, 0};
        #pragma unroll
        for (int q = 0; q < 4; q++) {
            if (v[q]) {
                double pv = (double)p[q], tv = (double)t[q], d = pv - tv;
                m[0] += pv; m[1] += pv * pv; m[2] += tv; m[3] += tv * tv;
                m[4] += d * d;
            }
        }
        #pragma unroll
        for (int q = 0; q < 5; q++) {
            #pragma unroll
            for (int o = 16; o > 0; o >>= 1)
                m[q] += __shfl_down_sync(0xFFFFFFFFu, m[q], o);
            if (lane == 0) smom[q][wid] = m[q];
        }
    }

    // ---- rank reduction ----
    double mine = 0.0;
    #pragma unroll
    for (int q = 0; q < 4; q++)
        if (v[q]) mine += (double)acch[q] + 0.1 * (double)accm[q];
    #pragma unroll
    for (int o = 16; o > 0; o >>= 1)
        mine += __shfl_down_sync(0xFFFFFFFFu, mine, o);
    if (lane == 0) swd[wid] = mine;
    __syncthreads();

    if (wid == 0) {
        double x = (lane < NWARP) ? swd[lane] : 0.0;
        #pragma unroll
        for (int o = 4; o > 0; o >>= 1)
            x += __shfl_down_sync(0xFFFFFFFFu, x, o);
        if (lane == 0) atomicAdd(&g_rank_sum, x);
    }
    if (momblk && wid == 1) {
        #pragma unroll
        for (int q = 0; q < 5; q++) {
            double x = (lane < NWARP) ? smom[q][lane] : 0.0;
            #pragma unroll
            for (int o = 4; o > 0; o >>= 1)
                x += __shfl_down_sync(0xFFFFFFFFu, x, o);
            if (lane == 0) g_mompart[I * 5 + q] = x;
        }
    }

    // ---- last-block finalize + reset (threadfence-reduction) ----
    if (tid == 0) {
        __threadfence();
        unsigned prev = atomicAdd(&g_done, 1u);
        s_last = (prev == (unsigned)(T - 1));
    }
    __syncthreads();

    if (s_last) {
        if (tid < Gi * 5) s_fin[tid] = g_mompart[tid];
        __syncthreads();
        if (tid == 0) {
            double M[5] = {0, 0, 0, 0, 0};
            for (int k = 0; k < Gi; k++)
                #pragma unroll
                for (int q = 0; q < 5; q++) M[q] += s_fin[k * 5 + q];
            double nn = (double)n;
            double mse  = M[4] / nn;
            double pvar = (M[1] - M[0] * M[0] / nn) / (nn - 1.0);
            double tvar = (M[3] - M[2] * M[2] / nn) / (nn - 1.0);
            double divl = fmax(tvar - pvar, 0.0);
            double pc   = nn * (nn - 1.0) * 0.5;
            double rank = g_rank_sum / pc;
            out[0] = (float)(0.1 * mse + 0.9 * rank + 0.1 * divl);
            g_rank_sum = 0.0;     // reset for next graph replay
            g_done = 0u;
        }
    }
}

extern "C" void kernel_launch(void* const* d_in, const int* in_sizes, int n_in,
                              void* d_out, int out_size) {
    const float* pred = (const float*)d_in[0];
    const float* targ = (const float*)d_in[1];
    int n = in_sizes[0];

    int Gi = (n + TI - 1) / TI;
    int Gj = (n + TJ - 1) / TJ;
    int T = 0;
    for (int I = 0; I < Gi; I++) T += Gj - RATIO * I;   // J in [RATIO*I, Gj)

    pair_kernel<<<T, TPB>>>(pred, targ, n, Gi, Gj, T, (float*)d_out);
}